// round 6
// baseline (speedup 1.0000x reference)
#include <cuda_runtime.h>
#include <math.h>

#define D     1024
#define SQ    1024          // sequence length
#define BB    4             // batch
#define NH    16            // heads
#define HDIM  64            // head dim
#define FFD   4096
#define NROWS 4096          // BB*SQ
#define EPSF  1e-7f
#define MAXT  0.99999f      // 1 - 1e-5 (as float)

// ---------------- scratch (static device memory; no runtime allocation) ----------------
__device__ __align__(16) float g_ada [BB*6*D];
__device__ __align__(16) float g_tm  [NROWS*D];
__device__ __align__(16) float g_lin [NROWS*D];
__device__ __align__(16) float g_qt  [NROWS*D];
__device__ __align__(16) float g_kt  [NROWS*D];
__device__ __align__(16) float g_vt  [NROWS*D];
__device__ __align__(16) float g_att [NROWS*D];
__device__ __align__(16) float g_tcat[NROWS*D];
__device__ __align__(16) float g_zb  [NROWS*D];
__device__ __align__(16) float g_xnew[NROWS*D];
// scores (B*H*S*S = 268MB), reused as FFN hidden (64MB)
__device__ __align__(16) float g_big [(size_t)BB*NH*SQ*SQ];

// ---------------- reduction helpers (blockDim == 256) ----------------
__device__ __forceinline__ float warp_sum(float v){
#pragma unroll
    for (int o=16;o;o>>=1) v += __shfl_xor_sync(0xffffffffu, v, o);
    return v;
}
__device__ __forceinline__ float warp_maxf(float v){
#pragma unroll
    for (int o=16;o;o>>=1) v = fmaxf(v, __shfl_xor_sync(0xffffffffu, v, o));
    return v;
}
__device__ __forceinline__ float blk_sum(float v, float* sb){
    int lane = threadIdx.x & 31, w = threadIdx.x >> 5;
    v = warp_sum(v);
    __syncthreads();                 // protect sb from previous use
    if (lane == 0) sb[w] = v;
    __syncthreads();
    float r = 0.f;
#pragma unroll
    for (int i=0;i<8;i++) r += sb[i];
    return r;
}
__device__ __forceinline__ float blk_max(float v, float* sb){
    int lane = threadIdx.x & 31, w = threadIdx.x >> 5;
    v = warp_maxf(v);
    __syncthreads();
    if (lane == 0) sb[w] = v;
    __syncthreads();
    float r = sb[0];
#pragma unroll
    for (int i=1;i<8;i++) r = fmaxf(r, sb[i]);
    return r;
}

// ---------------- ada = t_emb @ w_ada + b_ada ----------------
__global__ __launch_bounds__(256) void k_ada(const float* __restrict__ temb,
                                             const float* __restrict__ w,
                                             const float* __restrict__ bias){
    __shared__ float ts[D];
    int b = blockIdx.y;
    int j = blockIdx.x * 256 + threadIdx.x;     // 0..6143
    for (int i = threadIdx.x; i < D; i += 256) ts[i] = temb[b*D + i];
    __syncthreads();
    float acc = bias[j];
    const float* wp = w + j;
#pragma unroll 4
    for (int k = 0; k < D; k++) acc += ts[k] * wp[(size_t)k * (6*D)];
    g_ada[b*6*D + j] = acc;
}

// ---------------- logmap0 + layernorm + modulation + clipnorm ----------------
// out = clipnorm_D( LN(logmap0(P_row)) * (1 + sc) + sh )
__global__ __launch_bounds__(256) void k_prep(const float* __restrict__ P,
                                              int sh_off, int sc_off,
                                              float* __restrict__ out){
    __shared__ float sb[8];
    const float LC = atanhf(MAXT);
    int row = blockIdx.x, b = row >> 10;
    int t = threadIdx.x;
    const float* xr = P + (size_t)row * D;
    float x0[4];
#pragma unroll
    for (int i=0;i<4;i++) x0[i] = xr[t + i*256];
    float ss = 0.f;
#pragma unroll
    for (int i=0;i<4;i++) ss += x0[i]*x0[i];
    ss = blk_sum(ss, sb);
    float n  = fmaxf(sqrtf(ss), EPSF);
    float a  = fminf(fmaxf(n, EPSF), MAXT);
    float ls = atanhf(a) / n;                       // logmap0 scale
    float u[4];
#pragma unroll
    for (int i=0;i<4;i++) u[i] = x0[i]*ls;
    float m = blk_sum(u[0]+u[1]+u[2]+u[3], sb) * (1.0f/D);
    float vv = 0.f;
#pragma unroll
    for (int i=0;i<4;i++){ float d0 = u[i]-m; vv += d0*d0; }
    vv = blk_sum(vv, sb) * (1.0f/D);
    float inv = rsqrtf(vv + 1e-6f);
    const float* ad = g_ada + b*6*D;
    float v[4]; float s2 = 0.f;
#pragma unroll
    for (int i=0;i<4;i++){
        int d0 = t + i*256;
        float xn  = (u[i]-m)*inv;
        float val = xn * (1.0f + ad[sc_off + d0]) + ad[sh_off + d0];
        v[i] = val; s2 += val*val;
    }
    s2 = blk_sum(s2, sb);
    float nv = fmaxf(sqrtf(s2), EPSF);
    float cl = fminf(nv, LC) / nv;                  // logmap0(expmap0(.)) == norm clip
#pragma unroll
    for (int i=0;i<4;i++) out[(size_t)row*D + t + i*256] = v[i]*cl;
}

// ---------------- beta-split to heads (qt/kt/vt, layout [B,H,S,HD]) ----------------
// row -> clipnorm_D(row); per head: *R then clipnorm_HD
__global__ __launch_bounds__(256) void k_heads(const float* __restrict__ lin,
                                               float* __restrict__ out, float Rf){
    __shared__ float sb[8];
    const float LC = atanhf(MAXT);
    int row = blockIdx.x, b = row >> 10, s = row & 1023;
    int t = threadIdx.x, h = t >> 4, c = (t & 15) * 4;
    float4 z = *(const float4*)(lin + (size_t)row*D + h*HDIM + c);
    float ss = z.x*z.x + z.y*z.y + z.z*z.z + z.w*z.w;
    float tot = blk_sum(ss, sb);
    float n  = fmaxf(sqrtf(tot), EPSF);
    float s1 = fminf(n, LC)/n * Rf;
    float tx = z.x*s1, ty = z.y*s1, tz = z.z*s1, tw = z.w*s1;
    float hs = tx*tx + ty*ty + tz*tz + tw*tw;
#pragma unroll
    for (int o=1;o<16;o<<=1) hs += __shfl_xor_sync(0xffffffffu, hs, o);  // 16-thread segments = one head
    float nh = fmaxf(sqrtf(hs), EPSF);
    float s2 = fminf(nh, LC)/nh;
    float4 o4 = make_float4(tx*s2, ty*s2, tz*s2, tw*s2);
    *(float4*)(out + ((size_t)(b*NH + h)*SQ + s)*HDIM + c) = o4;
}

// ---------------- merge heads: clip_HD * Rinv, concat, clip_D ----------------
__global__ __launch_bounds__(256) void k_merge(const float* __restrict__ att,
                                               float* __restrict__ out, float Rinv){
    __shared__ float sb[8];
    const float LC = atanhf(MAXT);
    int row = blockIdx.x, b = row >> 10, s = row & 1023;
    int t = threadIdx.x, h = t >> 4, c = (t & 15) * 4;
    float4 z = *(const float4*)(att + ((size_t)(b*NH + h)*SQ + s)*HDIM + c);
    float hs = z.x*z.x + z.y*z.y + z.z*z.z + z.w*z.w;
#pragma unroll
    for (int o=1;o<16;o<<=1) hs += __shfl_xor_sync(0xffffffffu, hs, o);
    float nh = fmaxf(sqrtf(hs), EPSF);
    float s2 = fminf(nh, LC)/nh * Rinv;
    float tx = z.x*s2, ty = z.y*s2, tz = z.z*s2, tw = z.w*s2;
    float tot = blk_sum(tx*tx + ty*ty + tz*tz + tw*tw, sb);
    float n  = fmaxf(sqrtf(tot), EPSF);
    float s3 = fminf(n, LC)/n;
    float4 o4 = make_float4(tx*s3, ty*s3, tz*s3, tw*s3);
    *(float4*)(out + (size_t)row*D + h*HDIM + c) = o4;
}

// ---------------- softmax over last dim (1024), in place ----------------
__global__ __launch_bounds__(256) void k_softmax(float* __restrict__ sc){
    __shared__ float sb[8];
    size_t base = (size_t)blockIdx.x * SQ;
    int t = threadIdx.x;
    float x[4];
#pragma unroll
    for (int i=0;i<4;i++) x[i] = sc[base + t + i*256];
    float m = blk_max(fmaxf(fmaxf(x[0],x[1]), fmaxf(x[2],x[3])), sb);
    float e[4]; float s = 0.f;
#pragma unroll
    for (int i=0;i<4;i++){ e[i] = expf(x[i]-m); s += e[i]; }
    s = blk_sum(s, sb);
#pragma unroll
    for (int i=0;i<4;i++) sc[base + t + i*256] = e[i] / s;
}

// ---------------- clipnorm over FF=4096 row, in place ----------------
__global__ __launch_bounds__(256) void k_rownorm_ff(float* __restrict__ X){
    __shared__ float sb[8];
    const float LC = atanhf(MAXT);
    size_t base = (size_t)blockIdx.x * FFD;
    int t = threadIdx.x;
    float v[16]; float ss = 0.f;
#pragma unroll
    for (int i=0;i<16;i++){ v[i] = X[base + t + i*256]; ss += v[i]*v[i]; }
    ss = blk_sum(ss, sb);
    float n = fmaxf(sqrtf(ss), EPSF);
    float s1 = fminf(n, LC)/n;
#pragma unroll
    for (int i=0;i<16;i++) X[base + t + i*256] = v[i]*s1;
}

// ---------------- gate*clip, expmap0, mobius_add with residual ----------------
__global__ __launch_bounds__(256) void k_resmix(const float* __restrict__ Z, int g_off,
                                                const float* __restrict__ res,
                                                float* __restrict__ out){
    __shared__ float sb[8];
    const float LC = atanhf(MAXT);
    int row = blockIdx.x, b = row >> 10;
    int t = threadIdx.x;
    size_t base = (size_t)row * D;
    float z[4], r0[4], gg[4];
#pragma unroll
    for (int i=0;i<4;i++){
        int d0 = t + i*256;
        z[i]  = Z[base + d0];
        r0[i] = res[base + d0];
        gg[i] = g_ada[b*6*D + g_off + d0];
    }
    float ss = 0.f;
#pragma unroll
    for (int i=0;i<4;i++) ss += z[i]*z[i];
    ss = blk_sum(ss, sb);
    float n  = fmaxf(sqrtf(ss), EPSF);
    float s1 = fminf(n, LC)/n;                      // logmap0(expmap0(z))
    float tt[4]; float st = 0.f;
#pragma unroll
    for (int i=0;i<4;i++){ tt[i] = gg[i]*(z[i]*s1); st += tt[i]*tt[i]; }
    st = blk_sum(st, sb);
    float nt  = fmaxf(sqrtf(st), EPSF);
    float ysc = tanhf(nt)/nt;                        // expmap0
    float y[4];
#pragma unroll
    for (int i=0;i<4;i++) y[i] = tt[i]*ysc;
    float x2=0.f, y2=0.f, xy=0.f;
#pragma unroll
    for (int i=0;i<4;i++){ x2 += r0[i]*r0[i]; y2 += y[i]*y[i]; xy += r0[i]*y[i]; }
    x2 = blk_sum(x2, sb);
    y2 = blk_sum(y2, sb);
    xy = blk_sum(xy, sb);
    float den = fmaxf(1.0f + 2.0f*xy + x2*y2, EPSF);
    float ca  = 1.0f + 2.0f*xy + y2;
    float cb  = 1.0f - x2;
#pragma unroll
    for (int i=0;i<4;i++) out[base + t + i*256] = (ca*r0[i] + cb*y[i]) / den;
}

// ---------------- SGEMM: C = alpha*A@op(B) + bias, batched ----------------
// 128x128 block, BK=8, 8x8 per thread, 256 threads, double buffered.
// TB=false: B is [K,N] row-major.  TB=true: B is [N,K] row-major (C=A@B^T).
template<bool TB>
__global__ __launch_bounds__(256) void k_sgemm(
    const float* __restrict__ A, const float* __restrict__ Bm,
    const float* __restrict__ bias, float* __restrict__ C,
    int M, int N, int K, size_t sA, size_t sB, size_t sC, float alpha)
{
    __shared__ __align__(16) float As[2][8][128];
    __shared__ __align__(16) float Bs[2][8][128];
    const int tid = threadIdx.x;
    const float* Ab = A + (size_t)blockIdx.z * sA;
    const float* Bb = Bm + (size_t)blockIdx.z * sB;
    float* Cb = C + (size_t)blockIdx.z * sC;
    const int m0 = blockIdx.y * 128;
    const int n0 = blockIdx.x * 128;
    const int ar = tid >> 1;           // 0..127  (A / B^T row within tile)
    const int ac = (tid & 1) * 4;      // 0 or 4  (k offset)
    const int br = tid >> 5;           // 0..7    (B row, TB=false)
    const int bc = (tid & 31) * 4;     // 0..124  (B col, TB=false)
    const int tx = tid & 15, ty = tid >> 4;

    float acc[8][8];
#pragma unroll
    for (int i=0;i<8;i++)
#pragma unroll
        for (int j=0;j<8;j++) acc[i][j] = 0.f;

    const int KT = K >> 3;
    // prologue: load tile 0
    {
        float4 a4 = *(const float4*)(Ab + (size_t)(m0+ar)*K + ac);
        As[0][ac+0][ar]=a4.x; As[0][ac+1][ar]=a4.y; As[0][ac+2][ar]=a4.z; As[0][ac+3][ar]=a4.w;
        if (TB) {
            float4 b4 = make_float4(0.f,0.f,0.f,0.f);
            if (n0+ar < N) b4 = *(const float4*)(Bb + (size_t)(n0+ar)*K + ac);
            Bs[0][ac+0][ar]=b4.x; Bs[0][ac+1][ar]=b4.y; Bs[0][ac+2][ar]=b4.z; Bs[0][ac+3][ar]=b4.w;
        } else {
            float4 b4 = make_float4(0.f,0.f,0.f,0.f);
            if (n0+bc < N) b4 = *(const float4*)(Bb + (size_t)br*N + (n0+bc));
            *(float4*)&Bs[0][br][bc] = b4;
        }
    }
    __syncthreads();
    int buf = 0;
    for (int kb = 0; kb < KT; ++kb){
        float4 an = make_float4(0.f,0.f,0.f,0.f);
        float4 bn = make_float4(0.f,0.f,0.f,0.f);
        const bool has = (kb+1) < KT;
        if (has){
            int k0 = (kb+1) << 3;
            an = *(const float4*)(Ab + (size_t)(m0+ar)*K + k0 + ac);
            if (TB){
                if (n0+ar < N) bn = *(const float4*)(Bb + (size_t)(n0+ar)*K + k0 + ac);
            } else {
                if (n0+bc < N) bn = *(const float4*)(Bb + (size_t)(k0+br)*N + (n0+bc));
            }
        }
#pragma unroll
        for (int k=0;k<8;k++){
            float af[8], bf[8];
            *(float4*)(af)   = *(const float4*)(&As[buf][k][ty*8]);
            *(float4*)(af+4) = *(const float4*)(&As[buf][k][ty*8+4]);
            *(float4*)(bf)   = *(const float4*)(&Bs[buf][k][tx*8]);
            *(float4*)(bf+4) = *(const float4*)(&Bs[buf][k][tx*8+4]);
#pragma unroll
            for (int i=0;i<8;i++)
#pragma unroll
                for (int j=0;j<8;j++)
                    acc[i][j] += af[i]*bf[j];
        }
        if (has){
            int nb = buf ^ 1;
            As[nb][ac+0][ar]=an.x; As[nb][ac+1][ar]=an.y; As[nb][ac+2][ar]=an.z; As[nb][ac+3][ar]=an.w;
            if (TB){
                Bs[nb][ac+0][ar]=bn.x; Bs[nb][ac+1][ar]=bn.y; Bs[nb][ac+2][ar]=bn.z; Bs[nb][ac+3][ar]=bn.w;
            } else {
                *(float4*)&Bs[nb][br][bc] = bn;
            }
            __syncthreads();
            buf ^= 1;
        }
    }
    // epilogue
#pragma unroll
    for (int i=0;i<8;i++){
        int row = m0 + ty*8 + i;
        float* cr = Cb + (size_t)row * N;
#pragma unroll
        for (int j=0;j<8;j++){
            int col = n0 + tx*8 + j;
            if (col < N){
                float v = acc[i][j] * alpha;
                if (bias) v += bias[col];
                cr[col] = v;
            }
        }
    }
}

// ---------------- host launch ----------------
extern "C" void kernel_launch(void* const* d_in, const int* in_sizes, int n_in,
                              void* d_out, int out_size){
    (void)in_sizes; (void)n_in; (void)out_size;
    const float* x     = (const float*)d_in[0];
    const float* temb  = (const float*)d_in[1];
    const float* w_q   = (const float*)d_in[2];
    const float* b_q   = (const float*)d_in[3];
    const float* w_k   = (const float*)d_in[4];
    const float* b_k   = (const float*)d_in[5];
    const float* w_v   = (const float*)d_in[6];
    const float* b_v   = (const float*)d_in[7];
    const float* w_o   = (const float*)d_in[8];
    const float* b_o   = (const float*)d_in[9];
    const float* w_f1  = (const float*)d_in[10];
    const float* b_f1  = (const float*)d_in[11];
    const float* w_f2  = (const float*)d_in[12];
    const float* b_f2  = (const float*)d_in[13];
    const float* w_ada = (const float*)d_in[14];
    const float* b_ada = (const float*)d_in[15];
    float* out = (float*)d_out;

    float *tm, *lin, *qt, *kt, *vt, *att, *tcat, *zb, *xnew, *big;
    cudaGetSymbolAddress((void**)&tm,   g_tm);
    cudaGetSymbolAddress((void**)&lin,  g_lin);
    cudaGetSymbolAddress((void**)&qt,   g_qt);
    cudaGetSymbolAddress((void**)&kt,   g_kt);
    cudaGetSymbolAddress((void**)&vt,   g_vt);
    cudaGetSymbolAddress((void**)&att,  g_att);
    cudaGetSymbolAddress((void**)&tcat, g_tcat);
    cudaGetSymbolAddress((void**)&zb,   g_zb);
    cudaGetSymbolAddress((void**)&xnew, g_xnew);
    cudaGetSymbolAddress((void**)&big,  g_big);

    // beta(n/2, 1/2) ratios, same double-precision formula as reference
    double lgn = lgamma(512.0) + lgamma(0.5) - lgamma(512.5);
    double lgh = lgamma(32.0)  + lgamma(0.5) - lgamma(32.5);
    double betaN = exp(lgn), betaH = exp(lgh);
    float R    = (float)(betaH / betaN);
    float Rinv = (float)(betaN / betaH);

    // ada
    k_ada<<<dim3(24,4,1), 256>>>(temb, w_ada, b_ada);

    // ---- attention block ----
    k_prep<<<NROWS, 256>>>(x, /*sh*/0, /*sc*/D, tm);

    k_sgemm<false><<<dim3(8,32,1),256>>>(tm, w_q, b_q, lin, 4096,1024,1024, 0,0,0, 1.f);
    k_heads<<<NROWS,256>>>(lin, qt, R);
    k_sgemm<false><<<dim3(8,32,1),256>>>(tm, w_k, b_k, lin, 4096,1024,1024, 0,0,0, 1.f);
    k_heads<<<NROWS,256>>>(lin, kt, R);
    k_sgemm<false><<<dim3(8,32,1),256>>>(tm, w_v, b_v, lin, 4096,1024,1024, 0,0,0, 1.f);
    k_heads<<<NROWS,256>>>(lin, vt, R);

    // scores = qt @ kt^T / 8   (batched over B*H)
    k_sgemm<true><<<dim3(8,8,64),256>>>(qt, kt, nullptr, big, 1024,1024,64,
        (size_t)SQ*HDIM, (size_t)SQ*HDIM, (size_t)SQ*SQ, 0.125f);
    k_softmax<<<BB*NH*SQ, 256>>>(big);
    // att = P @ vt
    k_sgemm<false><<<dim3(1,8,64),256>>>(big, vt, nullptr, att, 1024,64,1024,
        (size_t)SQ*SQ, (size_t)SQ*HDIM, (size_t)SQ*HDIM, 1.f);

    k_merge<<<NROWS,256>>>(att, tcat, Rinv);
    k_sgemm<false><<<dim3(8,32,1),256>>>(tcat, w_o, b_o, zb, 4096,1024,1024, 0,0,0, 1.f);
    k_resmix<<<NROWS,256>>>(zb, /*gate*/2*D, x, xnew);

    // ---- FFN block ----
    k_prep<<<NROWS, 256>>>(xnew, /*sh*/3*D, /*sc*/4*D, tm);
    k_sgemm<false><<<dim3(32,32,1),256>>>(tm, w_f1, b_f1, big, 4096,4096,1024, 0,0,0, 1.f);
    k_rownorm_ff<<<NROWS,256>>>(big);
    k_sgemm<false><<<dim3(8,32,1),256>>>(big, w_f2, b_f2, zb, 4096,1024,4096, 0,0,0, 1.f);
    k_resmix<<<NROWS,256>>>(zb, /*gate*/5*D, xnew, out);
}

// round 7
// speedup vs baseline: 2.6733x; 2.6733x over previous
#include <cuda_runtime.h>
#include <math.h>

#define D     1024
#define SQ    1024          // sequence length
#define BB    4             // batch
#define NH    16            // heads
#define HDIM  64            // head dim
#define FFD   4096
#define NROWS 4096          // BB*SQ
#define EPSF  1e-7f
#define MAXT  0.99999f      // 1 - 1e-5 (as float)

// ---------------- scratch (static device memory; no runtime allocation) ----------------
__device__ __align__(16) float g_ada [BB*6*D];
__device__ __align__(16) float g_tm  [NROWS*D];
__device__ __align__(16) float g_lin [NROWS*D];
__device__ __align__(16) float g_qt  [NROWS*D];
__device__ __align__(16) float g_kt  [NROWS*D];
__device__ __align__(16) float g_vt  [NROWS*D];
__device__ __align__(16) float g_att [NROWS*D];
__device__ __align__(16) float g_tcat[NROWS*D];
__device__ __align__(16) float g_zb  [NROWS*D];
__device__ __align__(16) float g_xnew[NROWS*D];
// scores (B*H*S*S = 268MB), reused as FFN hidden (64MB)
__device__ __align__(16) float g_big [(size_t)BB*NH*SQ*SQ];

// ---------------- reduction helpers (blockDim == 256) ----------------
__device__ __forceinline__ float warp_sum(float v){
#pragma unroll
    for (int o=16;o;o>>=1) v += __shfl_xor_sync(0xffffffffu, v, o);
    return v;
}
__device__ __forceinline__ float warp_maxf(float v){
#pragma unroll
    for (int o=16;o;o>>=1) v = fmaxf(v, __shfl_xor_sync(0xffffffffu, v, o));
    return v;
}
__device__ __forceinline__ float blk_sum(float v, float* sb){
    int lane = threadIdx.x & 31, w = threadIdx.x >> 5;
    v = warp_sum(v);
    __syncthreads();
    if (lane == 0) sb[w] = v;
    __syncthreads();
    float r = 0.f;
#pragma unroll
    for (int i=0;i<8;i++) r += sb[i];
    return r;
}
__device__ __forceinline__ float blk_max(float v, float* sb){
    int lane = threadIdx.x & 31, w = threadIdx.x >> 5;
    v = warp_maxf(v);
    __syncthreads();
    if (lane == 0) sb[w] = v;
    __syncthreads();
    float r = sb[0];
#pragma unroll
    for (int i=1;i<8;i++) r = fmaxf(r, sb[i]);
    return r;
}

// ---------------- tf32 helpers ----------------
__device__ __forceinline__ unsigned f2t(float f){
    unsigned u; asm("cvt.rna.tf32.f32 %0, %1;" : "=r"(u) : "f"(f)); return u;
}
__device__ __forceinline__ uint4 cvt4(float4 v){
    return make_uint4(f2t(v.x), f2t(v.y), f2t(v.z), f2t(v.w));
}
__device__ __forceinline__ void mma_tf32(float* d, const unsigned* a, const unsigned* b){
    asm volatile("mma.sync.aligned.m16n8k8.row.col.f32.tf32.tf32.f32 "
        "{%0,%1,%2,%3}, {%4,%5,%6,%7}, {%8,%9}, {%0,%1,%2,%3};"
        : "+f"(d[0]), "+f"(d[1]), "+f"(d[2]), "+f"(d[3])
        : "r"(a[0]), "r"(a[1]), "r"(a[2]), "r"(a[3]), "r"(b[0]), "r"(b[1]));
}

// ---------------- ada = t_emb @ w_ada + b_ada ----------------
__global__ __launch_bounds__(256) void k_ada(const float* __restrict__ temb,
                                             const float* __restrict__ w,
                                             const float* __restrict__ bias){
    __shared__ float ts[D];
    int b = blockIdx.y;
    int j = blockIdx.x * 256 + threadIdx.x;
    for (int i = threadIdx.x; i < D; i += 256) ts[i] = temb[b*D + i];
    __syncthreads();
    float acc = bias[j];
    const float* wp = w + j;
#pragma unroll 4
    for (int k = 0; k < D; k++) acc += ts[k] * wp[(size_t)k * (6*D)];
    g_ada[b*6*D + j] = acc;
}

// ---------------- logmap0 + layernorm + modulation + clipnorm ----------------
__global__ __launch_bounds__(256) void k_prep(const float* __restrict__ P,
                                              int sh_off, int sc_off,
                                              float* __restrict__ out){
    __shared__ float sb[8];
    const float LC = atanhf(MAXT);
    int row = blockIdx.x, b = row >> 10;
    int t = threadIdx.x;
    const float* xr = P + (size_t)row * D;
    float x0[4];
#pragma unroll
    for (int i=0;i<4;i++) x0[i] = xr[t + i*256];
    float ss = 0.f;
#pragma unroll
    for (int i=0;i<4;i++) ss += x0[i]*x0[i];
    ss = blk_sum(ss, sb);
    float n  = fmaxf(sqrtf(ss), EPSF);
    float a  = fminf(fmaxf(n, EPSF), MAXT);
    float ls = atanhf(a) / n;
    float u[4];
#pragma unroll
    for (int i=0;i<4;i++) u[i] = x0[i]*ls;
    float m = blk_sum(u[0]+u[1]+u[2]+u[3], sb) * (1.0f/D);
    float vv = 0.f;
#pragma unroll
    for (int i=0;i<4;i++){ float d0 = u[i]-m; vv += d0*d0; }
    vv = blk_sum(vv, sb) * (1.0f/D);
    float inv = rsqrtf(vv + 1e-6f);
    const float* ad = g_ada + b*6*D;
    float v[4]; float s2 = 0.f;
#pragma unroll
    for (int i=0;i<4;i++){
        int d0 = t + i*256;
        float xn  = (u[i]-m)*inv;
        float val = xn * (1.0f + ad[sc_off + d0]) + ad[sh_off + d0];
        v[i] = val; s2 += val*val;
    }
    s2 = blk_sum(s2, sb);
    float nv = fmaxf(sqrtf(s2), EPSF);
    float cl = fminf(nv, LC) / nv;
#pragma unroll
    for (int i=0;i<4;i++) out[(size_t)row*D + t + i*256] = v[i]*cl;
}

// ---------------- beta-split to heads ----------------
__global__ __launch_bounds__(256) void k_heads(const float* __restrict__ lin,
                                               float* __restrict__ out, float Rf){
    __shared__ float sb[8];
    const float LC = atanhf(MAXT);
    int row = blockIdx.x, b = row >> 10, s = row & 1023;
    int t = threadIdx.x, h = t >> 4, c = (t & 15) * 4;
    float4 z = *(const float4*)(lin + (size_t)row*D + h*HDIM + c);
    float ss = z.x*z.x + z.y*z.y + z.z*z.z + z.w*z.w;
    float tot = blk_sum(ss, sb);
    float n  = fmaxf(sqrtf(tot), EPSF);
    float s1 = fminf(n, LC)/n * Rf;
    float tx = z.x*s1, ty = z.y*s1, tz = z.z*s1, tw = z.w*s1;
    float hs = tx*tx + ty*ty + tz*tz + tw*tw;
#pragma unroll
    for (int o=1;o<16;o<<=1) hs += __shfl_xor_sync(0xffffffffu, hs, o);
    float nh = fmaxf(sqrtf(hs), EPSF);
    float s2 = fminf(nh, LC)/nh;
    float4 o4 = make_float4(tx*s2, ty*s2, tz*s2, tw*s2);
    *(float4*)(out + ((size_t)(b*NH + h)*SQ + s)*HDIM + c) = o4;
}

// ---------------- merge heads ----------------
__global__ __launch_bounds__(256) void k_merge(const float* __restrict__ att,
                                               float* __restrict__ out, float Rinv){
    __shared__ float sb[8];
    const float LC = atanhf(MAXT);
    int row = blockIdx.x, b = row >> 10, s = row & 1023;
    int t = threadIdx.x, h = t >> 4, c = (t & 15) * 4;
    float4 z = *(const float4*)(att + ((size_t)(b*NH + h)*SQ + s)*HDIM + c);
    float hs = z.x*z.x + z.y*z.y + z.z*z.z + z.w*z.w;
#pragma unroll
    for (int o=1;o<16;o<<=1) hs += __shfl_xor_sync(0xffffffffu, hs, o);
    float nh = fmaxf(sqrtf(hs), EPSF);
    float s2 = fminf(nh, LC)/nh * Rinv;
    float tx = z.x*s2, ty = z.y*s2, tz = z.z*s2, tw = z.w*s2;
    float tot = blk_sum(tx*tx + ty*ty + tz*tz + tw*tw, sb);
    float n  = fmaxf(sqrtf(tot), EPSF);
    float s3 = fminf(n, LC)/n;
    float4 o4 = make_float4(tx*s3, ty*s3, tz*s3, tw*s3);
    *(float4*)(out + (size_t)row*D + h*HDIM + c) = o4;
}

// ---------------- softmax over last dim (1024), in place ----------------
__global__ __launch_bounds__(256) void k_softmax(float* __restrict__ sc){
    __shared__ float sb[8];
    size_t base = (size_t)blockIdx.x * SQ;
    int t = threadIdx.x;
    float x[4];
#pragma unroll
    for (int i=0;i<4;i++) x[i] = sc[base + t + i*256];
    float m = blk_max(fmaxf(fmaxf(x[0],x[1]), fmaxf(x[2],x[3])), sb);
    float e[4]; float s = 0.f;
#pragma unroll
    for (int i=0;i<4;i++){ e[i] = expf(x[i]-m); s += e[i]; }
    s = blk_sum(s, sb);
#pragma unroll
    for (int i=0;i<4;i++) sc[base + t + i*256] = e[i] / s;
}

// ---------------- clipnorm over FF=4096 row ----------------
__global__ __launch_bounds__(256) void k_rownorm_ff(float* __restrict__ X){
    __shared__ float sb[8];
    const float LC = atanhf(MAXT);
    size_t base = (size_t)blockIdx.x * FFD;
    int t = threadIdx.x;
    float v[16]; float ss = 0.f;
#pragma unroll
    for (int i=0;i<16;i++){ v[i] = X[base + t + i*256]; ss += v[i]*v[i]; }
    ss = blk_sum(ss, sb);
    float n = fmaxf(sqrtf(ss), EPSF);
    float s1 = fminf(n, LC)/n;
#pragma unroll
    for (int i=0;i<16;i++) X[base + t + i*256] = v[i]*s1;
}

// ---------------- gate*clip, expmap0, mobius_add with residual ----------------
__global__ __launch_bounds__(256) void k_resmix(const float* __restrict__ Z, int g_off,
                                                const float* __restrict__ res,
                                                float* __restrict__ out){
    __shared__ float sb[8];
    const float LC = atanhf(MAXT);
    int row = blockIdx.x, b = row >> 10;
    int t = threadIdx.x;
    size_t base = (size_t)row * D;
    float z[4], r0[4], gg[4];
#pragma unroll
    for (int i=0;i<4;i++){
        int d0 = t + i*256;
        z[i]  = Z[base + d0];
        r0[i] = res[base + d0];
        gg[i] = g_ada[b*6*D + g_off + d0];
    }
    float ss = 0.f;
#pragma unroll
    for (int i=0;i<4;i++) ss += z[i]*z[i];
    ss = blk_sum(ss, sb);
    float n  = fmaxf(sqrtf(ss), EPSF);
    float s1 = fminf(n, LC)/n;
    float tt[4]; float st = 0.f;
#pragma unroll
    for (int i=0;i<4;i++){ tt[i] = gg[i]*(z[i]*s1); st += tt[i]*tt[i]; }
    st = blk_sum(st, sb);
    float nt  = fmaxf(sqrtf(st), EPSF);
    float ysc = tanhf(nt)/nt;
    float y[4];
#pragma unroll
    for (int i=0;i<4;i++) y[i] = tt[i]*ysc;
    float x2=0.f, y2=0.f, xy=0.f;
#pragma unroll
    for (int i=0;i<4;i++){ x2 += r0[i]*r0[i]; y2 += y[i]*y[i]; xy += r0[i]*y[i]; }
    x2 = blk_sum(x2, sb);
    y2 = blk_sum(y2, sb);
    xy = blk_sum(xy, sb);
    float den = fmaxf(1.0f + 2.0f*xy + x2*y2, EPSF);
    float ca  = 1.0f + 2.0f*xy + y2;
    float cb  = 1.0f - x2;
#pragma unroll
    for (int i=0;i<4;i++) out[base + t + i*256] = (ca*r0[i] + cb*y[i]) / den;
}

// ---------------- TF32 tensor-core GEMM ----------------
// C = alpha*A@op(B) + bias, batched.  Block 128x128, BK=16, 256 threads
// (8 warps, 2x4; warp tile 64x32 = 4x4 m16n8k8 mma), register-staged
// double-buffered SMEM.
// TB=false: B is [K,N] row-major.  TB=true: B is [N,K] row-major (C = A@B^T).
#define AS_STRIDE 20   // 20 mod 32 => frag banks 4m+k, conflict-free
#define BS_STRIDE 136  // 136 mod 32 = 8 => frag banks 8tg+gid, conflict-free
template<bool TB>
__global__ __launch_bounds__(256) void k_mma(
    const float* __restrict__ A, const float* __restrict__ Bm,
    const float* __restrict__ bias, float* __restrict__ C,
    int M, int N, int K, size_t sA, size_t sB, size_t sC, float alpha)
{
    __shared__ unsigned As[2][128][AS_STRIDE];
    __shared__ unsigned Bs[2][16][BS_STRIDE];
    const int tid  = threadIdx.x;
    const int lane = tid & 31, wid = tid >> 5;
    const int wm = wid >> 2, wn = wid & 3;     // 2 (m) x 4 (n) warps
    const int gid = lane >> 2, tg = lane & 3;
    const float* Ab = A  + (size_t)blockIdx.z * sA;
    const float* Bb = Bm + (size_t)blockIdx.z * sB;
    float*       Cb = C  + (size_t)blockIdx.z * sC;
    const int m0 = blockIdx.y * 128;
    const int n0 = blockIdx.x * 128;

    float acc[4][4][4];
#pragma unroll
    for (int i=0;i<4;i++)
#pragma unroll
        for (int j=0;j<4;j++)
#pragma unroll
            for (int r=0;r<4;r++) acc[i][j][r] = 0.f;

    auto load_g = [&](int kb, uint4 (&ra)[2], uint4 (&rb)[2]){
#pragma unroll
        for (int it=0; it<2; it++){
            int row = it*64 + (tid>>2), c4 = (tid&3)*4;
            ra[it] = cvt4(*(const float4*)(Ab + (size_t)(m0+row)*K + kb + c4));
        }
        if (TB){
#pragma unroll
            for (int it=0; it<2; it++){
                int rn = it*64 + (tid>>2), c4 = (tid&3)*4;
                float4 v = make_float4(0.f,0.f,0.f,0.f);
                if (n0 + rn < N) v = *(const float4*)(Bb + (size_t)(n0+rn)*K + kb + c4);
                rb[it] = cvt4(v);
            }
        } else {
#pragma unroll
            for (int it=0; it<2; it++){
                int row = it*8 + (tid>>5), c4 = (tid&31)*4;
                float4 v = make_float4(0.f,0.f,0.f,0.f);
                if (n0 + c4 < N) v = *(const float4*)(Bb + (size_t)(kb+row)*N + n0 + c4);
                rb[it] = cvt4(v);
            }
        }
    };
    auto store_s = [&](int b, uint4 (&ra)[2], uint4 (&rb)[2]){
#pragma unroll
        for (int it=0; it<2; it++){
            int row = it*64 + (tid>>2), c4 = (tid&3)*4;
            *(uint4*)&As[b][row][c4] = ra[it];
        }
        if (TB){
#pragma unroll
            for (int it=0; it<2; it++){
                int rn = it*64 + (tid>>2), c4 = (tid&3)*4;
                Bs[b][c4+0][rn] = rb[it].x;
                Bs[b][c4+1][rn] = rb[it].y;
                Bs[b][c4+2][rn] = rb[it].z;
                Bs[b][c4+3][rn] = rb[it].w;
            }
        } else {
#pragma unroll
            for (int it=0; it<2; it++){
                int row = it*8 + (tid>>5), c4 = (tid&31)*4;
                *(uint4*)&Bs[b][row][c4] = rb[it];
            }
        }
    };
    auto comp = [&](int b){
#pragma unroll
        for (int ks=0; ks<16; ks+=8){
            unsigned af[4][4], bf[4][2];
#pragma unroll
            for (int im=0; im<4; im++){
                int mr = wm*64 + im*16 + gid;
                af[im][0] = As[b][mr  ][ks+tg  ];
                af[im][1] = As[b][mr+8][ks+tg  ];
                af[im][2] = As[b][mr  ][ks+tg+4];
                af[im][3] = As[b][mr+8][ks+tg+4];
            }
#pragma unroll
            for (int in=0; in<4; in++){
                int nc = wn*32 + in*8 + gid;
                bf[in][0] = Bs[b][ks+tg  ][nc];
                bf[in][1] = Bs[b][ks+tg+4][nc];
            }
#pragma unroll
            for (int im=0; im<4; im++)
#pragma unroll
                for (int in=0; in<4; in++)
                    mma_tf32(acc[im][in], af[im], bf[in]);
        }
    };

    {
        uint4 ra[2], rb[2];
        load_g(0, ra, rb);
        store_s(0, ra, rb);
    }
    __syncthreads();
    int buf = 0;
    for (int kb = 16; ; kb += 16){
        bool has = kb < K;
        uint4 ra[2], rb[2];
        if (has) load_g(kb, ra, rb);
        comp(buf);
        if (!has) break;
        store_s(buf^1, ra, rb);
        __syncthreads();
        buf ^= 1;
    }

    // epilogue
#pragma unroll
    for (int im=0; im<4; im++){
        int r0 = m0 + wm*64 + im*16 + gid;
#pragma unroll
        for (int in=0; in<4; in++){
            int c = n0 + wn*32 + in*8 + tg*2;
            if (c < N){
                float b0 = 0.f, b1 = 0.f;
                if (bias){ b0 = bias[c]; b1 = bias[c+1]; }
                *(float2*)(Cb + (size_t)r0*N + c) =
                    make_float2(acc[im][in][0]*alpha + b0, acc[im][in][1]*alpha + b1);
                *(float2*)(Cb + (size_t)(r0+8)*N + c) =
                    make_float2(acc[im][in][2]*alpha + b0, acc[im][in][3]*alpha + b1);
            }
        }
    }
}

// ---------------- host launch ----------------
extern "C" void kernel_launch(void* const* d_in, const int* in_sizes, int n_in,
                              void* d_out, int out_size){
    (void)in_sizes; (void)n_in; (void)out_size;
    const float* x     = (const float*)d_in[0];
    const float* temb  = (const float*)d_in[1];
    const float* w_q   = (const float*)d_in[2];
    const float* b_q   = (const float*)d_in[3];
    const float* w_k   = (const float*)d_in[4];
    const float* b_k   = (const float*)d_in[5];
    const float* w_v   = (const float*)d_in[6];
    const float* b_v   = (const float*)d_in[7];
    const float* w_o   = (const float*)d_in[8];
    const float* b_o   = (const float*)d_in[9];
    const float* w_f1  = (const float*)d_in[10];
    const float* b_f1  = (const float*)d_in[11];
    const float* w_f2  = (const float*)d_in[12];
    const float* b_f2  = (const float*)d_in[13];
    const float* w_ada = (const float*)d_in[14];
    const float* b_ada = (const float*)d_in[15];
    float* out = (float*)d_out;

    float *tm, *lin, *qt, *kt, *vt, *att, *tcat, *zb, *xnew, *big;
    cudaGetSymbolAddress((void**)&tm,   g_tm);
    cudaGetSymbolAddress((void**)&lin,  g_lin);
    cudaGetSymbolAddress((void**)&qt,   g_qt);
    cudaGetSymbolAddress((void**)&kt,   g_kt);
    cudaGetSymbolAddress((void**)&vt,   g_vt);
    cudaGetSymbolAddress((void**)&att,  g_att);
    cudaGetSymbolAddress((void**)&tcat, g_tcat);
    cudaGetSymbolAddress((void**)&zb,   g_zb);
    cudaGetSymbolAddress((void**)&xnew, g_xnew);
    cudaGetSymbolAddress((void**)&big,  g_big);

    double lgn = lgamma(512.0) + lgamma(0.5) - lgamma(512.5);
    double lgh = lgamma(32.0)  + lgamma(0.5) - lgamma(32.5);
    double betaN = exp(lgn), betaH = exp(lgh);
    float R    = (float)(betaH / betaN);
    float Rinv = (float)(betaN / betaH);

    // ada
    k_ada<<<dim3(24,4,1), 256>>>(temb, w_ada, b_ada);

    // ---- attention block ----
    k_prep<<<NROWS, 256>>>(x, /*sh*/0, /*sc*/D, tm);

    k_mma<false><<<dim3(8,32,1),256>>>(tm, w_q, b_q, lin, 4096,1024,1024, 0,0,0, 1.f);
    k_heads<<<NROWS,256>>>(lin, qt, R);
    k_mma<false><<<dim3(8,32,1),256>>>(tm, w_k, b_k, lin, 4096,1024,1024, 0,0,0, 1.f);
    k_heads<<<NROWS,256>>>(lin, kt, R);
    k_mma<false><<<dim3(8,32,1),256>>>(tm, w_v, b_v, lin, 4096,1024,1024, 0,0,0, 1.f);
    k_heads<<<NROWS,256>>>(lin, vt, R);

    // scores = qt @ kt^T / 8   (batched over B*H)
    k_mma<true><<<dim3(8,8,64),256>>>(qt, kt, nullptr, big, 1024,1024,64,
        (size_t)SQ*HDIM, (size_t)SQ*HDIM, (size_t)SQ*SQ, 0.125f);
    k_softmax<<<BB*NH*SQ, 256>>>(big);
    // att = P @ vt
    k_mma<false><<<dim3(1,8,64),256>>>(big, vt, nullptr, att, 1024,64,1024,
        (size_t)SQ*SQ, (size_t)SQ*HDIM, (size_t)SQ*HDIM, 1.f);

    k_merge<<<NROWS,256>>>(att, tcat, Rinv);
    k_mma<false><<<dim3(8,32,1),256>>>(tcat, w_o, b_o, zb, 4096,1024,1024, 0,0,0, 1.f);
    k_resmix<<<NROWS,256>>>(zb, /*gate*/2*D, x, xnew);

    // ---- FFN block ----
    k_prep<<<NROWS, 256>>>(xnew, /*sh*/3*D, /*sc*/4*D, tm);
    k_mma<false><<<dim3(32,32,1),256>>>(tm, w_f1, b_f1, big, 4096,4096,1024, 0,0,0, 1.f);
    k_rownorm_ff<<<NROWS,256>>>(big);
    k_mma<false><<<dim3(8,32,1),256>>>(big, w_f2, b_f2, zb, 4096,1024,4096, 0,0,0, 1.f);
    k_resmix<<<NROWS,256>>>(zb, /*gate*/5*D, xnew, out);
}

// round 11
// speedup vs baseline: 3.1090x; 1.1630x over previous
#include <cuda_runtime.h>
#include <math.h>

#define D     1024
#define SQ    1024          // sequence length
#define BB    4             // batch
#define NH    16            // heads
#define HDIM  64            // head dim
#define FFD   4096
#define NROWS 4096          // BB*SQ
#define EPSF  1e-7f
#define MAXT  0.99999f      // 1 - 1e-5 (as float)

// ---------------- scratch (static device memory; no runtime allocation) ----------------
__device__ __align__(16) float g_ada [BB*6*D];
__device__ __align__(16) float g_tm  [NROWS*D];
__device__ __align__(16) float g_lin [NROWS*D];
__device__ __align__(16) float g_qt  [NROWS*D];
__device__ __align__(16) float g_kt  [NROWS*D];
__device__ __align__(16) float g_vt  [NROWS*D];
__device__ __align__(16) float g_att [NROWS*D];
__device__ __align__(16) float g_tcat[NROWS*D];
__device__ __align__(16) float g_zb  [NROWS*D];
__device__ __align__(16) float g_xnew[NROWS*D];
// FFN hidden (4096 x 4096)
__device__ __align__(16) float g_big [(size_t)NROWS*FFD];

// ---------------- reduction helpers (blockDim == 256) ----------------
__device__ __forceinline__ float warp_sum(float v){
#pragma unroll
    for (int o=16;o;o>>=1) v += __shfl_xor_sync(0xffffffffu, v, o);
    return v;
}
__device__ __forceinline__ float warp_maxf(float v){
#pragma unroll
    for (int o=16;o;o>>=1) v = fmaxf(v, __shfl_xor_sync(0xffffffffu, v, o));
    return v;
}
__device__ __forceinline__ float blk_sum(float v, float* sb){
    int lane = threadIdx.x & 31, w = threadIdx.x >> 5;
    v = warp_sum(v);
    __syncthreads();
    if (lane == 0) sb[w] = v;
    __syncthreads();
    float r = 0.f;
#pragma unroll
    for (int i=0;i<8;i++) r += sb[i];
    return r;
}
__device__ __forceinline__ float blk_max(float v, float* sb){
    int lane = threadIdx.x & 31, w = threadIdx.x >> 5;
    v = warp_maxf(v);
    __syncthreads();
    if (lane == 0) sb[w] = v;
    __syncthreads();
    float r = sb[0];
#pragma unroll
    for (int i=1;i<8;i++) r = fmaxf(r, sb[i]);
    return r;
}

// ---------------- tf32 helpers ----------------
__device__ __forceinline__ unsigned f2t(float f){
    unsigned u; asm("cvt.rna.tf32.f32 %0, %1;" : "=r"(u) : "f"(f)); return u;
}
__device__ __forceinline__ uint4 cvt4(float4 v){
    return make_uint4(f2t(v.x), f2t(v.y), f2t(v.z), f2t(v.w));
}
__device__ __forceinline__ void mma_tf32(float* d, const unsigned* a, const unsigned* b){
    asm volatile("mma.sync.aligned.m16n8k8.row.col.f32.tf32.tf32.f32 "
        "{%0,%1,%2,%3}, {%4,%5,%6,%7}, {%8,%9}, {%0,%1,%2,%3};"
        : "+f"(d[0]), "+f"(d[1]), "+f"(d[2]), "+f"(d[3])
        : "r"(a[0]), "r"(a[1]), "r"(a[2]), "r"(a[3]), "r"(b[0]), "r"(b[1]));
}

// ---------------- ada = t_emb @ w_ada + b_ada ----------------
__global__ __launch_bounds__(256) void k_ada(const float* __restrict__ temb,
                                             const float* __restrict__ w,
                                             const float* __restrict__ bias){
    __shared__ float ts[D];
    int b = blockIdx.y;
    int j = blockIdx.x * 256 + threadIdx.x;
    for (int i = threadIdx.x; i < D; i += 256) ts[i] = temb[b*D + i];
    __syncthreads();
    float acc = bias[j];
    const float* wp = w + j;
#pragma unroll 4
    for (int k = 0; k < D; k++) acc += ts[k] * wp[(size_t)k * (6*D)];
    g_ada[b*6*D + j] = acc;
}

// ---------------- logmap0 + layernorm + modulation + clipnorm ----------------
__global__ __launch_bounds__(256) void k_prep(const float* __restrict__ P,
                                              int sh_off, int sc_off,
                                              float* __restrict__ out){
    __shared__ float sb[8];
    const float LC = atanhf(MAXT);
    int row = blockIdx.x, b = row >> 10;
    int t = threadIdx.x;
    const float* xr = P + (size_t)row * D;
    float x0[4];
#pragma unroll
    for (int i=0;i<4;i++) x0[i] = xr[t + i*256];
    float ss = 0.f;
#pragma unroll
    for (int i=0;i<4;i++) ss += x0[i]*x0[i];
    ss = blk_sum(ss, sb);
    float n  = fmaxf(sqrtf(ss), EPSF);
    float a  = fminf(fmaxf(n, EPSF), MAXT);
    float ls = atanhf(a) / n;
    float u[4];
#pragma unroll
    for (int i=0;i<4;i++) u[i] = x0[i]*ls;
    float m = blk_sum(u[0]+u[1]+u[2]+u[3], sb) * (1.0f/D);
    float vv = 0.f;
#pragma unroll
    for (int i=0;i<4;i++){ float d0 = u[i]-m; vv += d0*d0; }
    vv = blk_sum(vv, sb) * (1.0f/D);
    float inv = rsqrtf(vv + 1e-6f);
    const float* ad = g_ada + b*6*D;
    float v[4]; float s2 = 0.f;
#pragma unroll
    for (int i=0;i<4;i++){
        int d0 = t + i*256;
        float xn  = (u[i]-m)*inv;
        float val = xn * (1.0f + ad[sc_off + d0]) + ad[sh_off + d0];
        v[i] = val; s2 += val*val;
    }
    s2 = blk_sum(s2, sb);
    float nv = fmaxf(sqrtf(s2), EPSF);
    float cl = fminf(nv, LC) / nv;
#pragma unroll
    for (int i=0;i<4;i++) out[(size_t)row*D + t + i*256] = v[i]*cl;
}

// ---------------- beta-split to heads ----------------
__global__ __launch_bounds__(256) void k_heads(const float* __restrict__ lin,
                                               float* __restrict__ out, float Rf){
    __shared__ float sb[8];
    const float LC = atanhf(MAXT);
    int row = blockIdx.x, b = row >> 10, s = row & 1023;
    int t = threadIdx.x, h = t >> 4, c = (t & 15) * 4;
    float4 z = *(const float4*)(lin + (size_t)row*D + h*HDIM + c);
    float ss = z.x*z.x + z.y*z.y + z.z*z.z + z.w*z.w;
    float tot = blk_sum(ss, sb);
    float n  = fmaxf(sqrtf(tot), EPSF);
    float s1 = fminf(n, LC)/n * Rf;
    float tx = z.x*s1, ty = z.y*s1, tz = z.z*s1, tw = z.w*s1;
    float hs = tx*tx + ty*ty + tz*tz + tw*tw;
#pragma unroll
    for (int o=1;o<16;o<<=1) hs += __shfl_xor_sync(0xffffffffu, hs, o);
    float nh = fmaxf(sqrtf(hs), EPSF);
    float s2 = fminf(nh, LC)/nh;
    float4 o4 = make_float4(tx*s2, ty*s2, tz*s2, tw*s2);
    *(float4*)(out + ((size_t)(b*NH + h)*SQ + s)*HDIM + c) = o4;
}

// ---------------- merge heads ----------------
__global__ __launch_bounds__(256) void k_merge(const float* __restrict__ att,
                                               float* __restrict__ out, float Rinv){
    __shared__ float sb[8];
    const float LC = atanhf(MAXT);
    int row = blockIdx.x, b = row >> 10, s = row & 1023;
    int t = threadIdx.x, h = t >> 4, c = (t & 15) * 4;
    float4 z = *(const float4*)(att + ((size_t)(b*NH + h)*SQ + s)*HDIM + c);
    float hs = z.x*z.x + z.y*z.y + z.z*z.z + z.w*z.w;
#pragma unroll
    for (int o=1;o<16;o<<=1) hs += __shfl_xor_sync(0xffffffffu, hs, o);
    float nh = fmaxf(sqrtf(hs), EPSF);
    float s2 = fminf(nh, LC)/nh * Rinv;
    float tx = z.x*s2, ty = z.y*s2, tz = z.z*s2, tw = z.w*s2;
    float tot = blk_sum(tx*tx + ty*ty + tz*tz + tw*tw, sb);
    float n  = fmaxf(sqrtf(tot), EPSF);
    float s3 = fminf(n, LC)/n;
    float4 o4 = make_float4(tx*s3, ty*s3, tz*s3, tw*s3);
    *(float4*)(out + (size_t)row*D + h*HDIM + c) = o4;
}

// ---------------- clipnorm over FF=4096 row ----------------
__global__ __launch_bounds__(256) void k_rownorm_ff(float* __restrict__ X){
    __shared__ float sb[8];
    const float LC = atanhf(MAXT);
    size_t base = (size_t)blockIdx.x * FFD;
    int t = threadIdx.x;
    float v[16]; float ss = 0.f;
#pragma unroll
    for (int i=0;i<16;i++){ v[i] = X[base + t + i*256]; ss += v[i]*v[i]; }
    ss = blk_sum(ss, sb);
    float n = fmaxf(sqrtf(ss), EPSF);
    float s1 = fminf(n, LC)/n;
#pragma unroll
    for (int i=0;i<16;i++) X[base + t + i*256] = v[i]*s1;
}

// ---------------- gate*clip, expmap0, mobius_add with residual ----------------
__global__ __launch_bounds__(256) void k_resmix(const float* __restrict__ Z, int g_off,
                                                const float* __restrict__ res,
                                                float* __restrict__ out){
    __shared__ float sb[8];
    const float LC = atanhf(MAXT);
    int row = blockIdx.x, b = row >> 10;
    int t = threadIdx.x;
    size_t base = (size_t)row * D;
    float z[4], r0[4], gg[4];
#pragma unroll
    for (int i=0;i<4;i++){
        int d0 = t + i*256;
        z[i]  = Z[base + d0];
        r0[i] = res[base + d0];
        gg[i] = g_ada[b*6*D + g_off + d0];
    }
    float ss = 0.f;
#pragma unroll
    for (int i=0;i<4;i++) ss += z[i]*z[i];
    ss = blk_sum(ss, sb);
    float n  = fmaxf(sqrtf(ss), EPSF);
    float s1 = fminf(n, LC)/n;
    float tt[4]; float st = 0.f;
#pragma unroll
    for (int i=0;i<4;i++){ tt[i] = gg[i]*(z[i]*s1); st += tt[i]*tt[i]; }
    st = blk_sum(st, sb);
    float nt  = fmaxf(sqrtf(st), EPSF);
    float ysc = tanhf(nt)/nt;
    float y[4];
#pragma unroll
    for (int i=0;i<4;i++) y[i] = tt[i]*ysc;
    float x2=0.f, y2=0.f, xy=0.f;
#pragma unroll
    for (int i=0;i<4;i++){ x2 += r0[i]*r0[i]; y2 += y[i]*y[i]; xy += r0[i]*y[i]; }
    x2 = blk_sum(x2, sb);
    y2 = blk_sum(y2, sb);
    xy = blk_sum(xy, sb);
    float den = fmaxf(1.0f + 2.0f*xy + x2*y2, EPSF);
    float ca  = 1.0f + 2.0f*xy + y2;
    float cb  = 1.0f - x2;
#pragma unroll
    for (int i=0;i<4;i++) out[base + t + i*256] = (ca*r0[i] + cb*y[i]) / den;
}

// ---------------- fused flash attention (tf32 mma, online softmax) ----------------
// grid (SQ/128, BB*NH), 256 threads (8 warps x 16 q-rows).
// O[128,64] = softmax(Q Kt^T / 8) @ Vt, per (b,h), tiles of 128 kv rows.
// P accumulator frags feed PV mma directly as A-frags: accumulator columns
// {2t,2t+1} vs A-frag columns {t,t+4} absorbed by permuting V rows within
// each 8-row group at SMEM store: slot s holds V row {0,2,4,6,1,3,5,7}[s].
// Fragment layouts (m16n8k8, gid=lane>>2, tg=lane&3):
//   A: a0=(gid,tg) a1=(gid+8,tg) a2=(gid,tg+4) a3=(gid+8,tg+4)
//   B: b0=(k=tg,n=gid) b1=(k=tg+4,n=gid)
//   C: c0=(gid,2tg) c1=(gid,2tg+1) c2=(gid+8,2tg) c3=(gid+8,2tg+1)
#define QK_STRIDE 68   // 68 mod 32 = 4  -> frag banks 4*gid+tg, conflict-free
#define V_STRIDE  72   // 72 mod 32 = 8  -> frag banks 8*tg+gid, conflict-free
__global__ __launch_bounds__(256) void k_fattn(const float* __restrict__ qt,
                                               const float* __restrict__ kt,
                                               const float* __restrict__ vt,
                                               float* __restrict__ att){
    extern __shared__ unsigned smem_u[];
    unsigned* Qs = smem_u;                       // 128 x QK_STRIDE
    unsigned* Ks = smem_u + 128*QK_STRIDE;       // 128 x QK_STRIDE
    unsigned* Vs = smem_u + 2*128*QK_STRIDE;     // 128 x V_STRIDE

    const int tid = threadIdx.x, lane = tid & 31, wid = tid >> 5;
    const int gid = lane >> 2, tg = lane & 3;
    const int bh = blockIdx.y, q0 = blockIdx.x * 128;
    const float* Qb = qt + ((size_t)bh*SQ + q0)*HDIM;
    const float* Kb = kt + (size_t)bh*SQ*HDIM;
    const float* Vb = vt + (size_t)bh*SQ*HDIM;

    // load Q tile
#pragma unroll
    for (int it=0; it<8; it++){
        int row = it*16 + (tid>>4);
        int c4  = (tid & 15)*4;
        float4 v = *(const float4*)(Qb + (size_t)row*HDIM + c4);
        *(uint4*)&Qs[row*QK_STRIDE + c4] = cvt4(v);
    }

    float oacc[8][4];
#pragma unroll
    for (int i=0;i<8;i++){ oacc[i][0]=0.f; oacc[i][1]=0.f; oacc[i][2]=0.f; oacc[i][3]=0.f; }
    float m0 = -1e30f, m1 = -1e30f, l0 = 0.f, l1 = 0.f;
    const int qr = wid*16 + gid;

    for (int j=0; j<SQ/128; j++){
        __syncthreads();            // protect Ks/Vs from previous iter readers
        // load K/V tile j
#pragma unroll
        for (int it=0; it<8; it++){
            int row = it*16 + (tid>>4);
            int c4  = (tid & 15)*4;
            const float* kp = Kb + (size_t)(j*128+row)*HDIM + c4;
            *(uint4*)&Ks[row*QK_STRIDE + c4] = cvt4(*(const float4*)kp);
            const float* vp = Vb + (size_t)(j*128+row)*HDIM + c4;
            int r8 = row & 7;
            int s  = (r8 & 1) ? 4 + (r8>>1) : (r8>>1);   // perm_inv
            int pr = (row & ~7) | s;
            *(uint4*)&Vs[pr*V_STRIDE + c4] = cvt4(*(const float4*)vp);
        }
        __syncthreads();

        // S = Q @ K^T  (per warp: 16 x 128)
        float sf[16][4];
#pragma unroll
        for (int nt=0; nt<16; nt++){ sf[nt][0]=0.f; sf[nt][1]=0.f; sf[nt][2]=0.f; sf[nt][3]=0.f; }
#pragma unroll
        for (int ks=0; ks<8; ks++){
            unsigned a[4];
            a[0] = Qs[(qr  )*QK_STRIDE + ks*8 + tg  ];
            a[1] = Qs[(qr+8)*QK_STRIDE + ks*8 + tg  ];
            a[2] = Qs[(qr  )*QK_STRIDE + ks*8 + tg+4];
            a[3] = Qs[(qr+8)*QK_STRIDE + ks*8 + tg+4];
#pragma unroll
            for (int nt=0; nt<16; nt++){
                unsigned b[2];
                b[0] = Ks[(nt*8+gid)*QK_STRIDE + ks*8 + tg  ];
                b[1] = Ks[(nt*8+gid)*QK_STRIDE + ks*8 + tg+4];
                mma_tf32(sf[nt], a, b);
            }
        }
        // scale + online softmax (rows qr and qr+8; cols split across quad)
        float mx0 = -1e30f, mx1 = -1e30f;
#pragma unroll
        for (int nt=0; nt<16; nt++){
            sf[nt][0] *= 0.125f; sf[nt][1] *= 0.125f;
            sf[nt][2] *= 0.125f; sf[nt][3] *= 0.125f;
            mx0 = fmaxf(mx0, fmaxf(sf[nt][0], sf[nt][1]));   // row qr
            mx1 = fmaxf(mx1, fmaxf(sf[nt][2], sf[nt][3]));   // row qr+8
        }
        mx0 = fmaxf(mx0, __shfl_xor_sync(0xffffffffu, mx0, 1));
        mx0 = fmaxf(mx0, __shfl_xor_sync(0xffffffffu, mx0, 2));
        mx1 = fmaxf(mx1, __shfl_xor_sync(0xffffffffu, mx1, 1));
        mx1 = fmaxf(mx1, __shfl_xor_sync(0xffffffffu, mx1, 2));
        float m0n = fmaxf(m0, mx0), m1n = fmaxf(m1, mx1);
        float sc0 = __expf(m0 - m0n), sc1 = __expf(m1 - m1n);
        m0 = m0n; m1 = m1n;
        float rs0 = 0.f, rs1 = 0.f;
        unsigned paf[16][4];
#pragma unroll
        for (int nt=0; nt<16; nt++){
            float p0 = __expf(sf[nt][0] - m0n);   // (qr,   2tg)
            float p1 = __expf(sf[nt][1] - m0n);   // (qr,   2tg+1)
            float p2 = __expf(sf[nt][2] - m1n);   // (qr+8, 2tg)
            float p3 = __expf(sf[nt][3] - m1n);   // (qr+8, 2tg+1)
            rs0 += p0 + p1; rs1 += p2 + p3;
            // A-frag slots: a0=(qr,k=tg)->P(qr,2tg); a1=(qr+8,k=tg)->P(qr+8,2tg);
            //               a2=(qr,k=tg+4)->P(qr,2tg+1); a3=(qr+8,k=tg+4)->P(qr+8,2tg+1)
            paf[nt][0] = f2t(p0); paf[nt][1] = f2t(p2);
            paf[nt][2] = f2t(p1); paf[nt][3] = f2t(p3);
        }
        rs0 += __shfl_xor_sync(0xffffffffu, rs0, 1);
        rs0 += __shfl_xor_sync(0xffffffffu, rs0, 2);
        rs1 += __shfl_xor_sync(0xffffffffu, rs1, 1);
        rs1 += __shfl_xor_sync(0xffffffffu, rs1, 2);
        l0 = l0*sc0 + rs0; l1 = l1*sc1 + rs1;
#pragma unroll
        for (int d0=0; d0<8; d0++){
            oacc[d0][0] *= sc0; oacc[d0][1] *= sc0;   // row qr
            oacc[d0][2] *= sc1; oacc[d0][3] *= sc1;   // row qr+8
        }
        // O += P @ V   (V rows pre-permuted for the frag column trick)
#pragma unroll
        for (int ks=0; ks<16; ks++){
#pragma unroll
            for (int d0=0; d0<8; d0++){
                unsigned b[2];
                b[0] = Vs[(ks*8 + tg  )*V_STRIDE + d0*8 + gid];
                b[1] = Vs[(ks*8 + tg+4)*V_STRIDE + d0*8 + gid];
                mma_tf32(oacc[d0], paf[ks], b);
            }
        }
    }
    // epilogue: normalize, store.  C layout: c0=(qr,2tg) c1=(qr,2tg+1)
    // c2=(qr+8,2tg) c3=(qr+8,2tg+1)
    float il0 = 1.f / l0, il1 = 1.f / l1;
    float* Ob = att + ((size_t)bh*SQ + q0)*HDIM;
#pragma unroll
    for (int d0=0; d0<8; d0++){
        int c = d0*8 + 2*tg;
        *(float2*)(Ob + (size_t)qr*HDIM + c)     = make_float2(oacc[d0][0]*il0, oacc[d0][1]*il0);
        *(float2*)(Ob + (size_t)(qr+8)*HDIM + c) = make_float2(oacc[d0][2]*il1, oacc[d0][3]*il1);
    }
}

// ---------------- TF32 tensor-core GEMM ----------------
#define AS_STRIDE 20
#define BS_STRIDE 136
template<bool TB>
__global__ __launch_bounds__(256) void k_mma(
    const float* __restrict__ A, const float* __restrict__ Bm,
    const float* __restrict__ bias, float* __restrict__ C,
    int M, int N, int K, size_t sA, size_t sB, size_t sC, float alpha)
{
    __shared__ unsigned As[2][128][AS_STRIDE];
    __shared__ unsigned Bs[2][16][BS_STRIDE];
    const int tid  = threadIdx.x;
    const int lane = tid & 31, wid = tid >> 5;
    const int wm = wid >> 2, wn = wid & 3;
    const int gid = lane >> 2, tg = lane & 3;
    const float* Ab = A  + (size_t)blockIdx.z * sA;
    const float* Bb = Bm + (size_t)blockIdx.z * sB;
    float*       Cb = C  + (size_t)blockIdx.z * sC;
    const int m0 = blockIdx.y * 128;
    const int n0 = blockIdx.x * 128;

    float acc[4][4][4];
#pragma unroll
    for (int i=0;i<4;i++)
#pragma unroll
        for (int j=0;j<4;j++)
#pragma unroll
            for (int r=0;r<4;r++) acc[i][j][r] = 0.f;

    auto load_g = [&](int kb, uint4 (&ra)[2], uint4 (&rb)[2]){
#pragma unroll
        for (int it=0; it<2; it++){
            int row = it*64 + (tid>>2), c4 = (tid&3)*4;
            ra[it] = cvt4(*(const float4*)(Ab + (size_t)(m0+row)*K + kb + c4));
        }
        if (TB){
#pragma unroll
            for (int it=0; it<2; it++){
                int rn = it*64 + (tid>>2), c4 = (tid&3)*4;
                float4 v = make_float4(0.f,0.f,0.f,0.f);
                if (n0 + rn < N) v = *(const float4*)(Bb + (size_t)(n0+rn)*K + kb + c4);
                rb[it] = cvt4(v);
            }
        } else {
#pragma unroll
            for (int it=0; it<2; it++){
                int row = it*8 + (tid>>5), c4 = (tid&31)*4;
                float4 v = make_float4(0.f,0.f,0.f,0.f);
                if (n0 + c4 < N) v = *(const float4*)(Bb + (size_t)(kb+row)*N + n0 + c4);
                rb[it] = cvt4(v);
            }
        }
    };
    auto store_s = [&](int b, uint4 (&ra)[2], uint4 (&rb)[2]){
#pragma unroll
        for (int it=0; it<2; it++){
            int row = it*64 + (tid>>2), c4 = (tid&3)*4;
            *(uint4*)&As[b][row][c4] = ra[it];
        }
        if (TB){
#pragma unroll
            for (int it=0; it<2; it++){
                int rn = it*64 + (tid>>2), c4 = (tid&3)*4;
                Bs[b][c4+0][rn] = rb[it].x;
                Bs[b][c4+1][rn] = rb[it].y;
                Bs[b][c4+2][rn] = rb[it].z;
                Bs[b][c4+3][rn] = rb[it].w;
            }
        } else {
#pragma unroll
            for (int it=0; it<2; it++){
                int row = it*8 + (tid>>5), c4 = (tid&31)*4;
                *(uint4*)&Bs[b][row][c4] = rb[it];
            }
        }
    };
    auto comp = [&](int b){
#pragma unroll
        for (int ks=0; ks<16; ks+=8){
            unsigned af[4][4], bf[4][2];
#pragma unroll
            for (int im=0; im<4; im++){
                int mr = wm*64 + im*16 + gid;
                af[im][0] = As[b][mr  ][ks+tg  ];
                af[im][1] = As[b][mr+8][ks+tg  ];
                af[im][2] = As[b][mr  ][ks+tg+4];
                af[im][3] = As[b][mr+8][ks+tg+4];
            }
#pragma unroll
            for (int in=0; in<4; in++){
                int nc = wn*32 + in*8 + gid;
                bf[in][0] = Bs[b][ks+tg  ][nc];
                bf[in][1] = Bs[b][ks+tg+4][nc];
            }
#pragma unroll
            for (int im=0; im<4; im++)
#pragma unroll
                for (int in=0; in<4; in++)
                    mma_tf32(acc[im][in], af[im], bf[in]);
        }
    };

    {
        uint4 ra[2], rb[2];
        load_g(0, ra, rb);
        store_s(0, ra, rb);
    }
    __syncthreads();
    int buf = 0;
    for (int kb = 16; ; kb += 16){
        bool has = kb < K;
        uint4 ra[2], rb[2];
        if (has) load_g(kb, ra, rb);
        comp(buf);
        if (!has) break;
        store_s(buf^1, ra, rb);
        __syncthreads();
        buf ^= 1;
    }

#pragma unroll
    for (int im=0; im<4; im++){
        int r0 = m0 + wm*64 + im*16 + gid;
#pragma unroll
        for (int in=0; in<4; in++){
            int c = n0 + wn*32 + in*8 + tg*2;
            if (c < N){
                float b0 = 0.f, b1 = 0.f;
                if (bias){ b0 = bias[c]; b1 = bias[c+1]; }
                *(float2*)(Cb + (size_t)r0*N + c) =
                    make_float2(acc[im][in][0]*alpha + b0, acc[im][in][1]*alpha + b1);
                *(float2*)(Cb + (size_t)(r0+8)*N + c) =
                    make_float2(acc[im][in][2]*alpha + b0, acc[im][in][3]*alpha + b1);
            }
        }
    }
}

// ---------------- host launch ----------------
extern "C" void kernel_launch(void* const* d_in, const int* in_sizes, int n_in,
                              void* d_out, int out_size){
    (void)in_sizes; (void)n_in; (void)out_size;
    const float* x     = (const float*)d_in[0];
    const float* temb  = (const float*)d_in[1];
    const float* w_q   = (const float*)d_in[2];
    const float* b_q   = (const float*)d_in[3];
    const float* w_k   = (const float*)d_in[4];
    const float* b_k   = (const float*)d_in[5];
    const float* w_v   = (const float*)d_in[6];
    const float* b_v   = (const float*)d_in[7];
    const float* w_o   = (const float*)d_in[8];
    const float* b_o   = (const float*)d_in[9];
    const float* w_f1  = (const float*)d_in[10];
    const float* b_f1  = (const float*)d_in[11];
    const float* w_f2  = (const float*)d_in[12];
    const float* b_f2  = (const float*)d_in[13];
    const float* w_ada = (const float*)d_in[14];
    const float* b_ada = (const float*)d_in[15];
    float* out = (float*)d_out;

    float *tm, *lin, *qt, *kt, *vt, *att, *tcat, *zb, *xnew, *big;
    cudaGetSymbolAddress((void**)&tm,   g_tm);
    cudaGetSymbolAddress((void**)&lin,  g_lin);
    cudaGetSymbolAddress((void**)&qt,   g_qt);
    cudaGetSymbolAddress((void**)&kt,   g_kt);
    cudaGetSymbolAddress((void**)&vt,   g_vt);
    cudaGetSymbolAddress((void**)&att,  g_att);
    cudaGetSymbolAddress((void**)&tcat, g_tcat);
    cudaGetSymbolAddress((void**)&zb,   g_zb);
    cudaGetSymbolAddress((void**)&xnew, g_xnew);
    cudaGetSymbolAddress((void**)&big,  g_big);

    double lgn = lgamma(512.0) + lgamma(0.5) - lgamma(512.5);
    double lgh = lgamma(32.0)  + lgamma(0.5) - lgamma(32.5);
    double betaN = exp(lgn), betaH = exp(lgh);
    float R    = (float)(betaH / betaN);
    float Rinv = (float)(betaN / betaH);

    // flash-attn smem size (set every call; idempotent, not a stream op)
    const int fa_smem = (2*128*QK_STRIDE + 128*V_STRIDE) * 4;
    cudaFuncSetAttribute(k_fattn, cudaFuncAttributeMaxDynamicSharedMemorySize, fa_smem);

    // ada
    k_ada<<<dim3(24,4,1), 256>>>(temb, w_ada, b_ada);

    // ---- attention block ----
    k_prep<<<NROWS, 256>>>(x, /*sh*/0, /*sc*/D, tm);

    k_mma<false><<<dim3(8,32,1),256>>>(tm, w_q, b_q, lin, 4096,1024,1024, 0,0,0, 1.f);
    k_heads<<<NROWS,256>>>(lin, qt, R);
    k_mma<false><<<dim3(8,32,1),256>>>(tm, w_k, b_k, lin, 4096,1024,1024, 0,0,0, 1.f);
    k_heads<<<NROWS,256>>>(lin, kt, R);
    k_mma<false><<<dim3(8,32,1),256>>>(tm, w_v, b_v, lin, 4096,1024,1024, 0,0,0, 1.f);
    k_heads<<<NROWS,256>>>(lin, vt, R);

    // fused scores/softmax/PV
    k_fattn<<<dim3(SQ/128, BB*NH), 256, fa_smem>>>(qt, kt, vt, att);

    k_merge<<<NROWS,256>>>(att, tcat, Rinv);
    k_mma<false><<<dim3(8,32,1),256>>>(tcat, w_o, b_o, zb, 4096,1024,1024, 0,0,0, 1.f);
    k_resmix<<<NROWS,256>>>(zb, /*gate*/2*D, x, xnew);

    // ---- FFN block ----
    k_prep<<<NROWS, 256>>>(xnew, /*sh*/3*D, /*sc*/4*D, tm);
    k_mma<false><<<dim3(32,32,1),256>>>(tm, w_f1, b_f1, big, 4096,4096,1024, 0,0,0, 1.f);
    k_rownorm_ff<<<NROWS,256>>>(big);
    k_mma<false><<<dim3(8,32,1),256>>>(big, w_f2, b_f2, zb, 4096,1024,4096, 0,0,0, 1.f);
    k_resmix<<<NROWS,256>>>(zb, /*gate*/5*D, xnew, out);
}